// round 13
// baseline (speedup 1.0000x reference)
#include <cuda_runtime.h>
#include <cuda_fp16.h>

#define NN 100000
#define NE 1000000
#define NG 512
#define HID 64
#define SBLK 98          // setup kernel blocks (<=148 SMs -> co-resident)
#define STHR 1024
#define SGRID (SBLK * STHR)   // 100352 >= NN

// ---------------- scratch (static device globals; no allocation) ------------
__device__ unsigned g_cnt;            // grid-barrier counter (reset by k_out)
__device__ int    g_is64;
__device__ int    g_batch[NN];
__device__ int    g_indeg[NN];
__device__ int    g_rowstart[NN];
__device__ int    g_cursor[NN];
__device__ int    g_blk[SBLK];
__device__ unsigned long long g_csr[NE];      // packed (norm<<32 | src)
__device__ float  g_dinv[NN];
__device__ unsigned long long g_hh[NN * 16];  // h (layer-1 out), fp16 x4/slot
__device__ unsigned long long g_m[NN * 16];   // agg(h)+self, fp16 x4/slot
__device__ float4 g_sums4[NG * 16];
__device__ float  g_counts[NG];

__device__ __forceinline__ void red_add_v4(float4* a, float4 v) {
    asm volatile("red.global.add.v4.f32 [%0], {%1,%2,%3,%4};"
                 :: "l"(a), "f"(v.x), "f"(v.y), "f"(v.z), "f"(v.w)
                 : "memory");
}

__device__ __forceinline__ unsigned long long pack4h(float4 o) {
    __half2 ha = __floats2half2_rn(o.x, o.y);
    __half2 hb = __floats2half2_rn(o.z, o.w);
    unsigned ua = *reinterpret_cast<unsigned*>(&ha);
    unsigned ub = *reinterpret_cast<unsigned*>(&hb);
    return ((unsigned long long)ub << 32) | ua;
}

__device__ __forceinline__ float4 unpack4h(unsigned long long fv) {
    unsigned lo = (unsigned)fv, hi = (unsigned)(fv >> 32);
    float2 f0 = __half22float2(*reinterpret_cast<__half2*>(&lo));
    float2 f1 = __half22float2(*reinterpret_cast<__half2*>(&hi));
    return make_float4(f0.x, f0.y, f1.x, f1.y);
}

__device__ __forceinline__ void acc_edge(float4& acc, unsigned long long pk,
                                         unsigned long long fv) {
    float w = __uint_as_float((unsigned)(pk >> 32));
    float4 f = unpack4h(fv);
    acc.x += f.x * w; acc.y += f.y * w;
    acc.z += f.z * w; acc.w += f.w * w;
}

// software grid barrier: all SBLK blocks co-resident by construction
__device__ __forceinline__ void gbar(unsigned target) {
    __syncthreads();
    if (threadIdx.x == 0) {
        __threadfence();
        atomicAdd(&g_cnt, 1u);
        while (*((volatile unsigned*)&g_cnt) < target) { }
        __threadfence();
    }
    __syncthreads();
}

// ---------------- fused setup + layer-1 kernel -------------------------------
// phases: zero -> cvt -> scan(block) -> scan(top) -> finalize -> place -> l1
__global__ void __launch_bounds__(STHR, 1)
k_setup(const float* __restrict__ x, const float* __restrict__ W1,
        const float* __restrict__ b1, const void* ei_raw, const void* batch_raw) {
    __shared__ int sh[STHR];
    __shared__ float sW[192];
    __shared__ float sb[64];

    int t   = threadIdx.x;
    int gid = blockIdx.x * STHR + t;

    // ---- p0: zero + dtype detect ----
    if (gid == 0) {
        const long long* p = (const long long*)ei_raw;
        int ok = 1;
#pragma unroll
        for (int j = 0; j < 8; j++) {
            long long v = p[j];
            if (v < 0 || v >= NN) ok = 0;
        }
        g_is64 = ok;
    }
    if (gid < NN)      g_indeg[gid] = 0;
    if (gid < NG * 16) g_sums4[gid] = make_float4(0.f, 0.f, 0.f, 0.f);
    if (gid < NG)      g_counts[gid] = 0.0f;
    gbar(1 * SBLK);

    // ---- p1: degree + batch conversion ----
    int is64 = g_is64;
    for (int e = gid; e < NE; e += SGRID) {
        int d = is64 ? (int)((const long long*)ei_raw)[NE + e]
                     : ((const int*)ei_raw)[NE + e];
        atomicAdd(&g_indeg[d], 1);
    }
    if (gid < NN) {
        int b = is64 ? (int)((const long long*)batch_raw)[gid]
                     : ((const int*)batch_raw)[gid];
        g_batch[gid] = b;
        atomicAdd(&g_counts[b], 1.0f);
    }
    gbar(2 * SBLK);

    // ---- p2: block-level inclusive scan of indeg ----
    int deg = (gid < NN) ? g_indeg[gid] : 0;
    sh[t] = deg;
    __syncthreads();
#pragma unroll
    for (int off = 1; off < STHR; off <<= 1) {
        int cur = sh[t];
        int add = (t >= off) ? sh[t - off] : 0;
        __syncthreads();
        sh[t] = cur + add;
        __syncthreads();
    }
    int local_excl = sh[t] - deg;
    if (t == STHR - 1) g_blk[blockIdx.x] = sh[STHR - 1];
    gbar(3 * SBLK);

    // ---- p3: top-level scan of 98 block sums (block 0 only) ----
    if (blockIdx.x == 0) {
        if (t < 128) {
            int v = (t < SBLK) ? g_blk[t] : 0;
            sh[t] = v;
            __syncthreads();
#pragma unroll
            for (int off = 1; off < 128; off <<= 1) {
                int cur = sh[t];
                int add = (t >= off) ? sh[t - off] : 0;
                __syncthreads();
                sh[t] = cur + add;
                __syncthreads();
            }
            if (t < SBLK) g_blk[t] = sh[t] - v;   // exclusive
        } else {
            // must participate in block 0's __syncthreads inside the loop
            __syncthreads();
#pragma unroll
            for (int off = 1; off < 128; off <<= 1) { __syncthreads(); __syncthreads(); }
        }
    }
    gbar(4 * SBLK);

    // ---- p4: finalize rowstart / cursor / dinv ----
    if (gid < NN) {
        int row = local_excl + g_blk[blockIdx.x];
        g_rowstart[gid] = row;
        g_cursor[gid]   = row;
        g_dinv[gid]     = rsqrtf((float)deg + 1.0f);  // +1 self loop
    }
    gbar(5 * SBLK);

    // ---- p5: place edges into dst-ordered CSR ----
    for (int e = gid; e < NE; e += SGRID) {
        int s, d;
        if (is64) {
            const long long* p = (const long long*)ei_raw;
            s = (int)p[e]; d = (int)p[NE + e];
        } else {
            const int* p = (const int*)ei_raw;
            s = p[e]; d = p[NE + e];
        }
        float w = g_dinv[s] * g_dinv[d];
        int pos = atomicAdd(&g_cursor[d], 1);
        g_csr[pos] = ((unsigned long long)__float_as_uint(w) << 32) | (unsigned)s;
    }
    if (t < 192) sW[t] = __ldg(W1 + t);
    if (t < 64)  sb[t] = __ldg(b1 + t);
    gbar(6 * SBLK);

    // ---- p6: layer 1 (3-dim agg + W1 + b1 + relu -> fp16 h) ----
    int n = gid;
    if (n >= NN) return;
    int e   = g_rowstart[n];
    int end = e + g_indeg[n];
    float a0 = 0.f, a1 = 0.f, a2 = 0.f;
    for (; e + 2 <= end; e += 2) {
        unsigned long long pk0 = __ldg(&g_csr[e + 0]);
        unsigned long long pk1 = __ldg(&g_csr[e + 1]);
        int s0 = (int)(unsigned)pk0, s1 = (int)(unsigned)pk1;
        float w0 = __uint_as_float((unsigned)(pk0 >> 32));
        float w1 = __uint_as_float((unsigned)(pk1 >> 32));
        float p00 = __ldg(x + s0*3), p01 = __ldg(x + s0*3+1), p02 = __ldg(x + s0*3+2);
        float p10 = __ldg(x + s1*3), p11 = __ldg(x + s1*3+1), p12 = __ldg(x + s1*3+2);
        a0 += w0*p00 + w1*p10;
        a1 += w0*p01 + w1*p11;
        a2 += w0*p02 + w1*p12;
    }
    for (; e < end; e++) {
        unsigned long long pk = __ldg(&g_csr[e]);
        int s = (int)(unsigned)pk;
        float w = __uint_as_float((unsigned)(pk >> 32));
        a0 += w * __ldg(x + s*3);
        a1 += w * __ldg(x + s*3+1);
        a2 += w * __ldg(x + s*3+2);
    }
    float di = g_dinv[n];
    float sl = di * di;
    a0 += sl * __ldg(x + n*3);
    a1 += sl * __ldg(x + n*3+1);
    a2 += sl * __ldg(x + n*3+2);

#pragma unroll
    for (int c = 0; c < 16; c++) {
        float4 o;
        o.x = fmaxf(a0*sW[c*4+0] + a1*sW[64+c*4+0] + a2*sW[128+c*4+0] + sb[c*4+0], 0.f);
        o.y = fmaxf(a0*sW[c*4+1] + a1*sW[64+c*4+1] + a2*sW[128+c*4+1] + sb[c*4+1], 0.f);
        o.z = fmaxf(a0*sW[c*4+2] + a1*sW[64+c*4+2] + a2*sW[128+c*4+2] + sb[c*4+2], 0.f);
        o.w = fmaxf(a0*sW[c*4+3] + a1*sW[64+c*4+3] + a2*sW[128+c*4+3] + sb[c*4+3], 0.f);
        g_hh[n * 16 + c] = pack4h(o);
    }
}

// ---------------- remaining compute kernels ----------------------------------

// Layer 2 aggregation: m = agg(h) + h*dinv^2, fp16 in / fp16 out
__global__ void k_aggh() {
    int t = blockIdx.x * blockDim.x + threadIdx.x;
    if (t >= NN * 16) return;
    int n = t >> 4, c = t & 15;
    int e   = __ldg(g_rowstart + n);
    int end = e + __ldg(g_indeg + n);
    float4 acc = make_float4(0.f, 0.f, 0.f, 0.f);
    for (; e + 4 <= end; e += 4) {
        unsigned long long pk0 = __ldg(&g_csr[e + 0]);
        unsigned long long pk1 = __ldg(&g_csr[e + 1]);
        unsigned long long pk2 = __ldg(&g_csr[e + 2]);
        unsigned long long pk3 = __ldg(&g_csr[e + 3]);
        unsigned long long f0 = __ldg(&g_hh[((int)(unsigned)pk0) * 16 + c]);
        unsigned long long f1 = __ldg(&g_hh[((int)(unsigned)pk1) * 16 + c]);
        unsigned long long f2 = __ldg(&g_hh[((int)(unsigned)pk2) * 16 + c]);
        unsigned long long f3 = __ldg(&g_hh[((int)(unsigned)pk3) * 16 + c]);
        acc_edge(acc, pk0, f0);
        acc_edge(acc, pk1, f1);
        acc_edge(acc, pk2, f2);
        acc_edge(acc, pk3, f3);
    }
    for (; e < end; e++) {
        unsigned long long pk = __ldg(&g_csr[e]);
        unsigned long long fv = __ldg(&g_hh[((int)(unsigned)pk) * 16 + c]);
        acc_edge(acc, pk, fv);
    }
    float di = g_dinv[n];
    float sl = di * di;
    float4 self = unpack4h(__ldg(&g_hh[t]));
    acc.x += self.x * sl; acc.y += self.y * sl;
    acc.z += self.z * sl; acc.w += self.w * sl;
    g_m[t] = pack4h(acc);
}

// out-row = relu(m @ W2 + b2); fused mean-pool accumulation. 64 nodes/block.
__global__ void k_gemm2(const float* __restrict__ W2, const float* __restrict__ b2) {
    __shared__ float sW[64 * 64];
    __shared__ float sh[64 * 65];
    int t = threadIdx.x;
    int base = blockIdx.x * 64;

    float4* sW4 = (float4*)sW;
    const float4* W24 = (const float4*)W2;
    for (int i = t; i < 1024; i += 256) sW4[i] = __ldg(W24 + i);

    for (int i = t; i < 64 * 16; i += 256) {
        int nl = i >> 4, c = i & 15;
        int n = base + nl;
        float4 v = (n < NN) ? unpack4h(__ldg(&g_m[n * 16 + c]))
                            : make_float4(0.f, 0.f, 0.f, 0.f);
        sh[nl * 65 + c * 4 + 0] = v.x;
        sh[nl * 65 + c * 4 + 1] = v.y;
        sh[nl * 65 + c * 4 + 2] = v.z;
        sh[nl * 65 + c * 4 + 3] = v.w;
    }
    __syncthreads();

    int fg = t & 15, ns = t >> 4;
    float4 acc[4];
#pragma unroll
    for (int i = 0; i < 4; i++) acc[i] = make_float4(0.f, 0.f, 0.f, 0.f);

#pragma unroll 8
    for (int k = 0; k < 64; k++) {
        float4 w = sW4[k * 16 + fg];
#pragma unroll
        for (int i = 0; i < 4; i++) {
            float hv = sh[(ns * 4 + i) * 65 + k];
            acc[i].x += hv * w.x;
            acc[i].y += hv * w.y;
            acc[i].z += hv * w.z;
            acc[i].w += hv * w.w;
        }
    }

    float4 bb = __ldg((const float4*)b2 + fg);
#pragma unroll
    for (int i = 0; i < 4; i++) {
        int n = base + ns * 4 + i;
        if (n < NN) {
            float4 o;
            o.x = fmaxf(acc[i].x + bb.x, 0.f);
            o.y = fmaxf(acc[i].y + bb.y, 0.f);
            o.z = fmaxf(acc[i].z + bb.z, 0.f);
            o.w = fmaxf(acc[i].w + bb.w, 0.f);
            int g = __ldg(g_batch + n);
            red_add_v4(&g_sums4[g * 16 + fg], o);
        }
    }
}

__global__ void k_out(float4* __restrict__ out) {
    int t = blockIdx.x * blockDim.x + threadIdx.x;
    if (t == 0) g_cnt = 0;                 // reset grid barrier for next replay
    if (t >= NG * 16) return;
    int g = t >> 4;
    float inv = 1.0f / fmaxf(g_counts[g], 1.0f);
    float4 s = g_sums4[t];
    out[t] = make_float4(s.x * inv, s.y * inv, s.z * inv, s.w * inv);
}

// ---------------- launch ----------------------------------------------------

extern "C" void kernel_launch(void* const* d_in, const int* in_sizes, int n_in,
                              void* d_out, int out_size) {
    const float* x     = nullptr;
    const float* W1    = nullptr;
    const float* b1    = nullptr;
    const float* W2    = nullptr;
    const float* b2    = nullptr;
    const void*  ei    = nullptr;
    const void*  batch = nullptr;

    for (int i = 0; i < n_in; i++) {
        int sz = in_sizes[i];
        const void* p = d_in[i];
        switch (sz) {
            case 300000:  x     = (const float*)p; break;
            case 192:     W1    = (const float*)p; break;
            case 4096:    W2    = (const float*)p; break;
            case 2000000:
            case 4000000: ei    = p; break;
            case 100000:
            case 200000:  batch = p; break;
            case 64:
                if (!b1) b1 = (const float*)p;
                else     b2 = (const float*)p;
                break;
            default: break;
        }
    }

    const int TB = 256;
    const int gN16  = (NN * 16 + TB - 1) / TB;   // 6250
    const int gG    = (NG * 16 + TB - 1) / TB;   // 32
    const int gGemm = (NN + 63) / 64;            // 1563

    k_setup<<<SBLK, STHR>>>(x, W1, b1, ei, batch);  // setup + layer 1
    k_aggh<<<gN16, TB>>>();                          // layer 2 aggregation
    k_gemm2<<<gGemm, TB>>>(W2, b2);                  // W2 + bias + relu + pool
    k_out<<<gG, TB>>>((float4*)d_out);               // mean + barrier reset
}

// round 16
// speedup vs baseline: 1.6533x; 1.6533x over previous
#include <cuda_runtime.h>
#include <cuda_fp16.h>

#define NN 100000
#define NE 1000000
#define NG 512
#define HID 64
#define NBLK 98   // ceil(NN/1024)

// ---------------- scratch (static device globals; no allocation) ------------
__device__ int    g_is64;
__device__ int    g_batch[NN];
__device__ int    g_indeg[NN];
__device__ int    g_rowtmp[NN];
__device__ int    g_rowstart[NN];
__device__ int    g_cursor[NN];
__device__ int    g_blk[NBLK];
__device__ unsigned long long g_csr[NE];      // packed (norm<<32 | src)
__device__ float  g_dinv[NN];
__device__ float4 g_x4[NN];                   // packed x rows (x0,x1,x2,0)
__device__ unsigned long long g_hh[NN * 16];  // h (layer-1 out), fp16 x4/slot
__device__ unsigned long long g_m[NN * 16];   // agg(h)+self, fp16 x4/slot
__device__ float4 g_sums4[NG * 16];
__device__ float  g_counts[NG];

__device__ __forceinline__ void red_add_v4(float4* a, float4 v) {
    asm volatile("red.global.add.v4.f32 [%0], {%1,%2,%3,%4};"
                 :: "l"(a), "f"(v.x), "f"(v.y), "f"(v.z), "f"(v.w)
                 : "memory");
}

__device__ __forceinline__ unsigned long long pack4h(float4 o) {
    __half2 ha = __floats2half2_rn(o.x, o.y);
    __half2 hb = __floats2half2_rn(o.z, o.w);
    unsigned ua = *reinterpret_cast<unsigned*>(&ha);
    unsigned ub = *reinterpret_cast<unsigned*>(&hb);
    return ((unsigned long long)ub << 32) | ua;
}

__device__ __forceinline__ float4 unpack4h(unsigned long long fv) {
    unsigned lo = (unsigned)fv, hi = (unsigned)(fv >> 32);
    float2 f0 = __half22float2(*reinterpret_cast<__half2*>(&lo));
    float2 f1 = __half22float2(*reinterpret_cast<__half2*>(&hi));
    return make_float4(f0.x, f0.y, f1.x, f1.y);
}

__device__ __forceinline__ void acc_edge(float4& acc, unsigned long long pk,
                                         unsigned long long fv) {
    float w = __uint_as_float((unsigned)(pk >> 32));
    float4 f = unpack4h(fv);
    acc.x += f.x * w; acc.y += f.y * w;
    acc.z += f.z * w; acc.w += f.w * w;
}

// ---------------- setup kernels ---------------------------------------------

__global__ void k_init(const void* ei_raw) {
    int i = blockIdx.x * blockDim.x + threadIdx.x;
    if (i == 0) {
        const long long* p = (const long long*)ei_raw;
        int ok = 1;
#pragma unroll
        for (int j = 0; j < 8; j++) {
            long long v = p[j];
            if (v < 0 || v >= NN) ok = 0;
        }
        g_is64 = ok;
    }
    if (i < NN)      g_indeg[i] = 0;
    if (i < NG * 16) g_sums4[i] = make_float4(0.f, 0.f, 0.f, 0.f);
    if (i < NG)      g_counts[i] = 0.0f;
}

// degree + batch conversion + x packing
__global__ void k_cvt(const void* ei_raw, const void* batch_raw,
                      const float* __restrict__ x) {
    int i = blockIdx.x * blockDim.x + threadIdx.x;
    int is64 = g_is64;
    if (i < NE) {
        int d = is64 ? (int)((const long long*)ei_raw)[NE + i]
                     : ((const int*)ei_raw)[NE + i];
        atomicAdd(&g_indeg[d], 1);
    }
    if (i < NN) {
        int b = is64 ? (int)((const long long*)batch_raw)[i]
                     : ((const int*)batch_raw)[i];
        g_batch[i] = b;
        atomicAdd(&g_counts[b], 1.0f);
        g_x4[i] = make_float4(__ldg(x + i*3), __ldg(x + i*3+1),
                              __ldg(x + i*3+2), 0.f);
    }
}

// warp-shuffle block scan of indeg (1024 threads/block)
__global__ void k_scan1() {
    __shared__ int warpsum[32];
    int t = threadIdx.x;
    int lane = t & 31, w = t >> 5;
    int n = blockIdx.x * 1024 + t;
    int deg = (n < NN) ? g_indeg[n] : 0;

    int v = deg;
#pragma unroll
    for (int off = 1; off < 32; off <<= 1) {
        int u = __shfl_up_sync(0xFFFFFFFFu, v, off);
        if (lane >= off) v += u;
    }
    if (lane == 31) warpsum[w] = v;
    __syncthreads();
    if (w == 0) {
        int s = warpsum[lane];
#pragma unroll
        for (int off = 1; off < 32; off <<= 1) {
            int u = __shfl_up_sync(0xFFFFFFFFu, s, off);
            if (lane >= off) s += u;
        }
        warpsum[lane] = s;
    }
    __syncthreads();
    int incl = v + (w > 0 ? warpsum[w - 1] : 0);
    if (n < NN) g_rowtmp[n] = incl - deg;            // exclusive within block
    if (t == 1023) g_blk[blockIdx.x] = incl;         // block total
}

// scan of the 98 block sums (single warp, shuffle + sequential tiles)
__global__ void k_scan2() {
    int lane = threadIdx.x;   // 32 threads
    int carry = 0;
    for (int base = 0; base < NBLK; base += 32) {
        int i = base + lane;
        int v = (i < NBLK) ? g_blk[i] : 0;
        int s = v;
#pragma unroll
        for (int off = 1; off < 32; off <<= 1) {
            int u = __shfl_up_sync(0xFFFFFFFFu, s, off);
            if (lane >= off) s += u;
        }
        if (i < NBLK) g_blk[i] = carry + s - v;      // exclusive
        carry += __shfl_sync(0xFFFFFFFFu, s, 31);
    }
}

// finalize rowstart/cursor + dinv
__global__ void k_scan3() {
    int n = blockIdx.x * blockDim.x + threadIdx.x;
    if (n < NN) {
        int row = g_rowtmp[n] + g_blk[n >> 10];
        g_rowstart[n] = row;
        g_cursor[n]   = row;
        g_dinv[n]     = rsqrtf((float)g_indeg[n] + 1.0f);  // +1 self loop
    }
}

// place edges into dst-ordered CSR with precomputed norm
__global__ void k_place(const void* ei_raw) {
    int e = blockIdx.x * blockDim.x + threadIdx.x;
    if (e >= NE) return;
    int s, d;
    if (g_is64) {
        const long long* p = (const long long*)ei_raw;
        s = (int)p[e]; d = (int)p[NE + e];
    } else {
        const int* p = (const int*)ei_raw;
        s = p[e]; d = p[NE + e];
    }
    float w = g_dinv[s] * g_dinv[d];
    int pos = atomicAdd(&g_cursor[d], 1);
    g_csr[pos] = ((unsigned long long)__float_as_uint(w) << 32) | (unsigned)s;
}

// ---------------- compute kernels -------------------------------------------

// Layer 1, thread-per-node: aggregate packed x over in-edges, add self,
// then apply W1 + b1 + ReLU; store h as fp16.
__global__ void k_l1(const float* __restrict__ W1, const float* __restrict__ b1) {
    __shared__ float sW[192];
    __shared__ float sb[64];
    int t = threadIdx.x;
    if (t < 192) sW[t] = __ldg(W1 + t);
    if (t < 64)  sb[t] = __ldg(b1 + t);
    __syncthreads();

    int n = blockIdx.x * blockDim.x + t;
    if (n >= NN) return;

    int e   = __ldg(g_rowstart + n);
    int end = e + __ldg(g_indeg + n);
    float a0 = 0.f, a1 = 0.f, a2 = 0.f;
    for (; e + 4 <= end; e += 4) {
        unsigned long long pk0 = __ldg(&g_csr[e + 0]);
        unsigned long long pk1 = __ldg(&g_csr[e + 1]);
        unsigned long long pk2 = __ldg(&g_csr[e + 2]);
        unsigned long long pk3 = __ldg(&g_csr[e + 3]);
        float4 p0 = __ldg(&g_x4[(int)(unsigned)pk0]);
        float4 p1 = __ldg(&g_x4[(int)(unsigned)pk1]);
        float4 p2 = __ldg(&g_x4[(int)(unsigned)pk2]);
        float4 p3 = __ldg(&g_x4[(int)(unsigned)pk3]);
        float w0 = __uint_as_float((unsigned)(pk0 >> 32));
        float w1 = __uint_as_float((unsigned)(pk1 >> 32));
        float w2 = __uint_as_float((unsigned)(pk2 >> 32));
        float w3 = __uint_as_float((unsigned)(pk3 >> 32));
        a0 += w0*p0.x + w1*p1.x + w2*p2.x + w3*p3.x;
        a1 += w0*p0.y + w1*p1.y + w2*p2.y + w3*p3.y;
        a2 += w0*p0.z + w1*p1.z + w2*p2.z + w3*p3.z;
    }
    for (; e < end; e++) {
        unsigned long long pk = __ldg(&g_csr[e]);
        float4 p = __ldg(&g_x4[(int)(unsigned)pk]);
        float w = __uint_as_float((unsigned)(pk >> 32));
        a0 += w * p.x; a1 += w * p.y; a2 += w * p.z;
    }
    // self term
    float di = g_dinv[n];
    float sl = di * di;
    float4 ps = __ldg(&g_x4[n]);
    a0 += sl * ps.x; a1 += sl * ps.y; a2 += sl * ps.z;

#pragma unroll
    for (int c = 0; c < 16; c++) {
        float4 o;
        o.x = fmaxf(a0*sW[c*4+0] + a1*sW[64+c*4+0] + a2*sW[128+c*4+0] + sb[c*4+0], 0.f);
        o.y = fmaxf(a0*sW[c*4+1] + a1*sW[64+c*4+1] + a2*sW[128+c*4+1] + sb[c*4+1], 0.f);
        o.z = fmaxf(a0*sW[c*4+2] + a1*sW[64+c*4+2] + a2*sW[128+c*4+2] + sb[c*4+2], 0.f);
        o.w = fmaxf(a0*sW[c*4+3] + a1*sW[64+c*4+3] + a2*sW[128+c*4+3] + sb[c*4+3], 0.f);
        g_hh[n * 16 + c] = pack4h(o);
    }
}

// Layer 2 aggregation: m = agg(h) + h*dinv^2, fp16 in / fp16 out
__global__ void k_aggh() {
    int t = blockIdx.x * blockDim.x + threadIdx.x;
    if (t >= NN * 16) return;
    int n = t >> 4, c = t & 15;
    int e   = __ldg(g_rowstart + n);
    int end = e + __ldg(g_indeg + n);
    float4 acc = make_float4(0.f, 0.f, 0.f, 0.f);
    for (; e + 4 <= end; e += 4) {
        unsigned long long pk0 = __ldg(&g_csr[e + 0]);
        unsigned long long pk1 = __ldg(&g_csr[e + 1]);
        unsigned long long pk2 = __ldg(&g_csr[e + 2]);
        unsigned long long pk3 = __ldg(&g_csr[e + 3]);
        unsigned long long f0 = __ldg(&g_hh[((int)(unsigned)pk0) * 16 + c]);
        unsigned long long f1 = __ldg(&g_hh[((int)(unsigned)pk1) * 16 + c]);
        unsigned long long f2 = __ldg(&g_hh[((int)(unsigned)pk2) * 16 + c]);
        unsigned long long f3 = __ldg(&g_hh[((int)(unsigned)pk3) * 16 + c]);
        acc_edge(acc, pk0, f0);
        acc_edge(acc, pk1, f1);
        acc_edge(acc, pk2, f2);
        acc_edge(acc, pk3, f3);
    }
    for (; e < end; e++) {
        unsigned long long pk = __ldg(&g_csr[e]);
        unsigned long long fv = __ldg(&g_hh[((int)(unsigned)pk) * 16 + c]);
        acc_edge(acc, pk, fv);
    }
    float di = g_dinv[n];
    float sl = di * di;
    float4 self = unpack4h(__ldg(&g_hh[t]));
    acc.x += self.x * sl; acc.y += self.y * sl;
    acc.z += self.z * sl; acc.w += self.w * sl;
    g_m[t] = pack4h(acc);
}

// out-row = relu(m @ W2 + b2); fused mean-pool accumulation. 64 nodes/block.
__global__ void k_gemm2(const float* __restrict__ W2, const float* __restrict__ b2) {
    __shared__ float sW[64 * 64];
    __shared__ float sh[64 * 65];
    int t = threadIdx.x;
    int base = blockIdx.x * 64;

    float4* sW4 = (float4*)sW;
    const float4* W24 = (const float4*)W2;
    for (int i = t; i < 1024; i += 256) sW4[i] = __ldg(W24 + i);

    for (int i = t; i < 64 * 16; i += 256) {
        int nl = i >> 4, c = i & 15;
        int n = base + nl;
        float4 v = (n < NN) ? unpack4h(__ldg(&g_m[n * 16 + c]))
                            : make_float4(0.f, 0.f, 0.f, 0.f);
        sh[nl * 65 + c * 4 + 0] = v.x;
        sh[nl * 65 + c * 4 + 1] = v.y;
        sh[nl * 65 + c * 4 + 2] = v.z;
        sh[nl * 65 + c * 4 + 3] = v.w;
    }
    __syncthreads();

    int fg = t & 15, ns = t >> 4;
    float4 acc[4];
#pragma unroll
    for (int i = 0; i < 4; i++) acc[i] = make_float4(0.f, 0.f, 0.f, 0.f);

#pragma unroll 8
    for (int k = 0; k < 64; k++) {
        float4 w = sW4[k * 16 + fg];
#pragma unroll
        for (int i = 0; i < 4; i++) {
            float hv = sh[(ns * 4 + i) * 65 + k];
            acc[i].x += hv * w.x;
            acc[i].y += hv * w.y;
            acc[i].z += hv * w.z;
            acc[i].w += hv * w.w;
        }
    }

    float4 bb = __ldg((const float4*)b2 + fg);
#pragma unroll
    for (int i = 0; i < 4; i++) {
        int n = base + ns * 4 + i;
        if (n < NN) {
            float4 o;
            o.x = fmaxf(acc[i].x + bb.x, 0.f);
            o.y = fmaxf(acc[i].y + bb.y, 0.f);
            o.z = fmaxf(acc[i].z + bb.z, 0.f);
            o.w = fmaxf(acc[i].w + bb.w, 0.f);
            int g = __ldg(g_batch + n);
            red_add_v4(&g_sums4[g * 16 + fg], o);
        }
    }
}

__global__ void k_out(float4* __restrict__ out) {
    int t = blockIdx.x * blockDim.x + threadIdx.x;
    if (t >= NG * 16) return;
    int g = t >> 4;
    float inv = 1.0f / fmaxf(g_counts[g], 1.0f);
    float4 s = g_sums4[t];
    out[t] = make_float4(s.x * inv, s.y * inv, s.z * inv, s.w * inv);
}

// ---------------- launch ----------------------------------------------------

extern "C" void kernel_launch(void* const* d_in, const int* in_sizes, int n_in,
                              void* d_out, int out_size) {
    const float* x     = nullptr;
    const float* W1    = nullptr;
    const float* b1    = nullptr;
    const float* W2    = nullptr;
    const float* b2    = nullptr;
    const void*  ei    = nullptr;
    const void*  batch = nullptr;

    for (int i = 0; i < n_in; i++) {
        int sz = in_sizes[i];
        const void* p = d_in[i];
        switch (sz) {
            case 300000:  x     = (const float*)p; break;
            case 192:     W1    = (const float*)p; break;
            case 4096:    W2    = (const float*)p; break;
            case 2000000:
            case 4000000: ei    = p; break;
            case 100000:
            case 200000:  batch = p; break;
            case 64:
                if (!b1) b1 = (const float*)p;
                else     b2 = (const float*)p;
                break;
            default: break;
        }
    }

    const int TB = 256;
    const int gN    = (NN + TB - 1) / TB;        // 391
    const int gE    = (NE + TB - 1) / TB;        // 3907
    const int gN16  = (NN * 16 + TB - 1) / TB;   // 6250
    const int gG    = (NG * 16 + TB - 1) / TB;   // 32
    const int gGemm = (NN + 63) / 64;            // 1563

    k_init<<<gN, TB>>>(ei);
    k_cvt<<<gE, TB>>>(ei, batch, x);
    k_scan1<<<NBLK, 1024>>>();
    k_scan2<<<1, 32>>>();
    k_scan3<<<gN, TB>>>();
    k_place<<<gE, TB>>>(ei);

    k_l1<<<gN, TB>>>(W1, b1);         // layer 1: 3-dim agg + W1 + relu
    k_aggh<<<gN16, TB>>>();           // layer 2 aggregation (64-dim)
    k_gemm2<<<gGemm, TB>>>(W2, b2);   // W2 + bias + relu + fused pool

    k_out<<<gG, TB>>>((float4*)d_out);
}